// round 13
// baseline (speedup 1.0000x reference)
#include <cuda_runtime.h>

#define H_IMG 512
#define W_IMG 512
#define NPLANES 96            // 32 * 3
#define TW 32
#define TH 32
#define IW 42                 // TW + 10
#define IH 42                 // TH + 10
#define SS2 43                // staged (g,r) pair stride
#define MS2 33                // intermediate pair stride
#define NT 256
#define NBX 16                // 512/32
#define NBY 16                // 512/32
#define NBLK (NBX * NBY * NPLANES)   // 24576
#define C1F 6.5025f
#define C2F 58.5225f
#define NPIX 25165824.0       // 32*3*512*512

typedef unsigned long long u64;

__device__ float g_partials[NBLK];
__device__ unsigned int g_count = 0;

#define W11_INIT {0.00102838f, 0.00759871f, 0.03600077f, 0.10936070f, \
                  0.21300560f, 0.26601180f, 0.21300560f, 0.10936070f, \
                  0.03600077f, 0.00759871f, 0.00102838f}

__forceinline__ __device__ u64 ffma2(u64 a, u64 b, u64 c) {
    u64 d;
    asm("fma.rn.f32x2 %0, %1, %2, %3;" : "=l"(d) : "l"(a), "l"(b), "l"(c));
    return d;
}
__forceinline__ __device__ u64 pack2(float lo, float hi) {
    u64 d;
    asm("mov.b64 %0, {%1, %2};" : "=l"(d) : "f"(lo), "f"(hi));
    return d;
}
__forceinline__ __device__ void unpack2(u64 v, float& lo, float& hi) {
    asm("mov.b64 {%0, %1}, %2;" : "=f"(lo), "=f"(hi) : "l"(v));
}

__global__ void __launch_bounds__(NT, 5) ssim_main(const float* __restrict__ gen,
                                                   const float* __restrict__ ref,
                                                   float* __restrict__ out) {
    __shared__ u64 sgr[IH * SS2];      // packed (g, r), scaled
    __shared__ u64 pm[IH * MS2];       // packed (conv_h g, conv_h r)
    __shared__ u64 pv[IH * MS2];       // packed (conv_h g^2+r^2, conv_h g*r)
    __shared__ u64 ws2[11];            // packed (w, w)
    __shared__ float wsum[8];
    __shared__ double dsum[8];
    __shared__ bool is_last;

    const float W11[11] = W11_INIT;

    const int tid = threadIdx.x;
    const int lane = tid & 31;
    const int wrp = tid >> 5;
    const int x0 = blockIdx.x * TW;
    const int y0 = blockIdx.y * TH;
    const size_t pb = (size_t)blockIdx.z * (size_t)(H_IMG * W_IMG);
    const float* gp = gen + pb;
    const float* rp = ref + pb;

    if (tid < 11) ws2[tid] = pack2(W11[tid], W11[tid]);

    // ---- Stage 0: warp-per-row coalesced load, scale, pack (g,r), zero-pad ----
    const bool interior = (x0 >= 5) & (x0 + IW - 5 <= W_IMG) &
                          (y0 >= 5) & (y0 + IH - 5 <= H_IMG);
    if (interior) {
        const float* gb = gp + (long)(y0 - 5) * W_IMG + (x0 - 5);
        const float* rb = rp + (long)(y0 - 5) * W_IMG + (x0 - 5);
#pragma unroll
        for (int r = wrp; r < IH; r += 8) {
            const float* grow = gb + (long)r * W_IMG;
            const float* rrow = rb + (long)r * W_IMG;
            u64* srow = sgr + r * SS2;
            srow[lane] = pack2(fmaf(grow[lane], 0.5f, 0.5f),
                               fmaf(rrow[lane], 0.5f, 0.5f));
            if (lane < IW - 32)
                srow[lane + 32] = pack2(fmaf(grow[lane + 32], 0.5f, 0.5f),
                                        fmaf(rrow[lane + 32], 0.5f, 0.5f));
        }
    } else {
#pragma unroll
        for (int r = wrp; r < IH; r += 8) {
            int gy = y0 + r - 5;
            bool rowok = (unsigned)gy < (unsigned)H_IMG;
            const float* grow = gp + (long)gy * W_IMG;
            const float* rrow = rp + (long)gy * W_IMG;
            u64* srow = sgr + r * SS2;
#pragma unroll
            for (int h = 0; h < 2; h++) {
                int c = lane + h * 32;
                if (c < IW) {
                    int gx = x0 + c - 5;
                    bool ok = rowok && ((unsigned)gx < (unsigned)W_IMG);
                    srow[c] = ok ? pack2(fmaf(grow[gx], 0.5f, 0.5f),
                                         fmaf(rrow[gx], 0.5f, 0.5f))
                                 : 0ull;
                }
            }
        }
    }
    __syncthreads();

    // ---- Stage 1: packed horizontal conv, row-fastest map (conflict-free) ----
    for (int item = tid; item < IH * 8; item += NT) {
        int ch = item / IH;
        int r = item - ch * IH;
        int c0 = ch << 2;
        const u64* srow = sgr + r * SS2 + c0;
        const int o = r * MS2 + c0;

        u64 w[14];
#pragma unroll
        for (int t = 0; t < 14; t++) w[t] = srow[t];

        // first moments (g, r) packed
        {
            u64 s[4] = {0ull, 0ull, 0ull, 0ull};
#pragma unroll
            for (int k = 0; k < 11; k++) {
                u64 wt = ws2[k];
#pragma unroll
                for (int j = 0; j < 4; j++) s[j] = ffma2(wt, w[k + j], s[j]);
            }
#pragma unroll
            for (int j = 0; j < 4; j++) pm[o + j] = s[j];
        }

        // in-place transform: w <- (g^2 + r^2, g*r)
#pragma unroll
        for (int t = 0; t < 14; t++) {
            float gv, rv;
            unpack2(w[t], gv, rv);
            w[t] = pack2(fmaf(gv, gv, rv * rv), gv * rv);
        }

        // second moments (ss, gr) packed
        {
            u64 s[4] = {0ull, 0ull, 0ull, 0ull};
#pragma unroll
            for (int k = 0; k < 11; k++) {
                u64 wt = ws2[k];
#pragma unroll
                for (int j = 0; j < 4; j++) s[j] = ffma2(wt, w[k + j], s[j]);
            }
#pragma unroll
            for (int j = 0; j < 4; j++) pv[o + j] = s[j];
        }
    }
    __syncthreads();

    // ---- Stage 2: packed vertical conv (4 rows/thread) + streaming SSIM ----
    float lsum = 0.f;
    {
        const int c = lane;
        const int r0 = wrp << 2;       // 8 warps * 4 rows = 32

        float q[4], p[4];              // mu1^2+mu2^2, mu1*mu2
        {
            u64 v[14];
#pragma unroll
            for (int t = 0; t < 14; t++) v[t] = pm[(r0 + t) * MS2 + c];
            u64 acc[4] = {0ull, 0ull, 0ull, 0ull};
#pragma unroll
            for (int k = 0; k < 11; k++) {
                u64 wt = ws2[k];
#pragma unroll
                for (int j = 0; j < 4; j++) acc[j] = ffma2(wt, v[j + k], acc[j]);
            }
#pragma unroll
            for (int j = 0; j < 4; j++) {
                float o1, o2;
                unpack2(acc[j], o1, o2);
                q[j] = fmaf(o1, o1, o2 * o2);
                p[j] = o1 * o2;
            }
        }
        {
            u64 v[14];
#pragma unroll
            for (int t = 0; t < 14; t++) v[t] = pv[(r0 + t) * MS2 + c];
            u64 acc[4] = {0ull, 0ull, 0ull, 0ull};
#pragma unroll
            for (int k = 0; k < 11; k++) {
                u64 wt = ws2[k];
#pragma unroll
                for (int j = 0; j < 4; j++) acc[j] = ffma2(wt, v[j + k], acc[j]);
            }
#pragma unroll
            for (int j = 0; j < 4; j++) {
                float oss, ogr;
                unpack2(acc[j], oss, ogr);
                float num = fmaf(2.f, p[j], C1F) * fmaf(2.f, ogr - p[j], C2F);
                float den = (q[j] + C1F) * (oss - q[j] + C2F);
                lsum += __fdividef(num, den);
            }
        }
    }

    // ---- Block reduction (fp32) ----
#pragma unroll
    for (int off = 16; off > 0; off >>= 1)
        lsum += __shfl_xor_sync(0xffffffffu, lsum, off);
    if (lane == 0) wsum[wrp] = lsum;
    __syncthreads();

    if (tid == 0) {
        float s = 0.f;
#pragma unroll
        for (int i = 0; i < 8; i++) s += wsum[i];
        int bid = blockIdx.x + NBX * (blockIdx.y + NBY * blockIdx.z);
        g_partials[bid] = s;
        __threadfence();
        unsigned int t = atomicAdd(&g_count, 1u);
        is_last = (t == (unsigned)(NBLK - 1));
    }
    __syncthreads();

    // ---- Last block: deterministic final reduction ----
    if (is_last) {
        __threadfence();
        double acc = 0.0;
        for (int i = tid; i < NBLK; i += NT)
            acc += (double)g_partials[i];
#pragma unroll
        for (int off = 16; off > 0; off >>= 1)
            acc += __shfl_xor_sync(0xffffffffu, acc, off);
        if (lane == 0) dsum[wrp] = acc;
        __syncthreads();
        if (tid == 0) {
            double s = 0.0;
#pragma unroll
            for (int i = 0; i < 8; i++) s += dsum[i];
            out[0] = (float)(1.0 - s / NPIX);
            g_count = 0;   // self-reset -> graph-replay deterministic
        }
    }
}

extern "C" void kernel_launch(void* const* d_in, const int* in_sizes, int n_in,
                              void* d_out, int out_size) {
    const float* gen = (const float*)d_in[0];
    const float* ref = (const float*)d_in[1];
    float* out = (float*)d_out;

    dim3 grid(NBX, NBY, NPLANES);
    ssim_main<<<grid, NT>>>(gen, ref, out);
}

// round 14
// speedup vs baseline: 1.1197x; 1.1197x over previous
#include <cuda_runtime.h>

#define H_IMG 512
#define W_IMG 512
#define NPLANES 96            // 32 * 3
#define TW 32
#define TH 32
#define IW 42                 // TW + 10
#define IH 42                 // TH + 10
#define SS2 43                // staged (g,r) float2 stride
#define MS2 33                // intermediate float2 stride
#define NT 256
#define NBX 16                // 512/32
#define NBY 16                // 512/32
#define NTILES (NBX * NBY * NPLANES)   // 24576
#define NPERS 740             // 148 SMs x 5 resident CTAs
#define C1F 6.5025f
#define C2F 58.5225f
#define NPIX 25165824.0       // 32*3*512*512

__device__ float g_partials[NPERS];
__device__ unsigned int g_count = 0;

#define W11_INIT {0.00102838f, 0.00759871f, 0.03600077f, 0.10936070f, \
                  0.21300560f, 0.26601180f, 0.21300560f, 0.10936070f, \
                  0.03600077f, 0.00759871f, 0.00102838f}

__global__ void __launch_bounds__(NT, 5) ssim_main(const float* __restrict__ gen,
                                                   const float* __restrict__ ref,
                                                   float* __restrict__ out) {
    __shared__ float2 sgr[IH * SS2];   // (g, r) scaled
    __shared__ float2 pm[IH * MS2];    // (conv_h g, conv_h r)
    __shared__ float2 pv[IH * MS2];    // (conv_h g^2+r^2, conv_h g*r)
    __shared__ float wsum[8];
    __shared__ double dsum[8];
    __shared__ bool is_last;

    const float W11[11] = W11_INIT;    // compile-time consts -> FFMA-imm

    const int tid = threadIdx.x;
    const int lane = tid & 31;
    const int wrp = tid >> 5;
    const int bid = blockIdx.x;

    float lsum = 0.f;                  // accumulated across all tiles of this block

    for (int tile = bid; tile < NTILES; tile += NPERS) {
        // tile decode: all power-of-2 -> shifts
        const int bx = tile & (NBX - 1);
        const int by = (tile >> 4) & (NBY - 1);
        const int bz = tile >> 8;
        const int x0 = bx * TW;
        const int y0 = by * TH;
        const size_t pb = (size_t)bz * (size_t)(H_IMG * W_IMG);
        const float* gp = gen + pb;
        const float* rp = ref + pb;

        // ---- Stage 0: warp-per-row coalesced load, scale, pack, zero-pad ----
        const bool interior = (x0 >= 5) & (x0 + IW - 5 <= W_IMG) &
                              (y0 >= 5) & (y0 + IH - 5 <= H_IMG);
        if (interior) {
            const float* gb = gp + (long)(y0 - 5) * W_IMG + (x0 - 5);
            const float* rb = rp + (long)(y0 - 5) * W_IMG + (x0 - 5);
#pragma unroll
            for (int r = wrp; r < IH; r += 8) {
                const float* grow = gb + (long)r * W_IMG;
                const float* rrow = rb + (long)r * W_IMG;
                float2* srow = sgr + r * SS2;
                srow[lane] = make_float2(fmaf(grow[lane], 0.5f, 0.5f),
                                         fmaf(rrow[lane], 0.5f, 0.5f));
                if (lane < IW - 32)
                    srow[lane + 32] = make_float2(fmaf(grow[lane + 32], 0.5f, 0.5f),
                                                  fmaf(rrow[lane + 32], 0.5f, 0.5f));
            }
        } else {
#pragma unroll
            for (int r = wrp; r < IH; r += 8) {
                int gy = y0 + r - 5;
                bool rowok = (unsigned)gy < (unsigned)H_IMG;
                const float* grow = gp + (long)gy * W_IMG;
                const float* rrow = rp + (long)gy * W_IMG;
                float2* srow = sgr + r * SS2;
#pragma unroll
                for (int h = 0; h < 2; h++) {
                    int c = lane + h * 32;
                    if (c < IW) {
                        int gx = x0 + c - 5;
                        bool ok = rowok && ((unsigned)gx < (unsigned)W_IMG);
                        srow[c] = ok ? make_float2(fmaf(grow[gx], 0.5f, 0.5f),
                                                   fmaf(rrow[gx], 0.5f, 0.5f))
                                     : make_float2(0.f, 0.f);
                    }
                }
            }
        }
        __syncthreads();   // also orders prior tile's stage-2 reads before stage-1 writes

        // ---- Stage 1: horizontal conv, row-fastest map (conflict-free) ----
        for (int item = tid; item < IH * 8; item += NT) {
            int ch = item / IH;
            int r = item - ch * IH;
            int c0 = ch << 2;
            const float2* srow = sgr + r * SS2 + c0;
            const int o = r * MS2 + c0;

            float2 w[14];
#pragma unroll
            for (int t = 0; t < 14; t++) w[t] = srow[t];

            // first moments (g, r)
            {
                float s1[4] = {0.f, 0.f, 0.f, 0.f};
                float s2[4] = {0.f, 0.f, 0.f, 0.f};
#pragma unroll
                for (int k = 0; k < 11; k++) {
#pragma unroll
                    for (int j = 0; j < 4; j++) {
                        s1[j] = fmaf(W11[k], w[k + j].x, s1[j]);
                        s2[j] = fmaf(W11[k], w[k + j].y, s2[j]);
                    }
                }
#pragma unroll
                for (int j = 0; j < 4; j++) pm[o + j] = make_float2(s1[j], s2[j]);
            }

            // in-place transform: w <- (g^2 + r^2, g*r)
#pragma unroll
            for (int t = 0; t < 14; t++) {
                float gv = w[t].x;
                float rv = w[t].y;
                w[t] = make_float2(fmaf(gv, gv, rv * rv), gv * rv);
            }

            // second moments (ss, gr)
            {
                float s3[4] = {0.f, 0.f, 0.f, 0.f};
                float s4[4] = {0.f, 0.f, 0.f, 0.f};
#pragma unroll
                for (int k = 0; k < 11; k++) {
#pragma unroll
                    for (int j = 0; j < 4; j++) {
                        s3[j] = fmaf(W11[k], w[k + j].x, s3[j]);
                        s4[j] = fmaf(W11[k], w[k + j].y, s4[j]);
                    }
                }
#pragma unroll
                for (int j = 0; j < 4; j++) pv[o + j] = make_float2(s3[j], s4[j]);
            }
        }
        __syncthreads();

        // ---- Stage 2: vertical conv (4 rows/thread), streaming SSIM ----
        {
            const int c = lane;
            const int r0 = wrp << 2;   // 8 warps * 4 rows = 32

            float q[4], p[4];          // mu1^2+mu2^2, mu1*mu2
            {
                float2 v[14];
#pragma unroll
                for (int t = 0; t < 14; t++) v[t] = pm[(r0 + t) * MS2 + c];
#pragma unroll
                for (int j = 0; j < 4; j++) {
                    float o1 = 0.f, o2 = 0.f;
#pragma unroll
                    for (int k = 0; k < 11; k++) {
                        o1 = fmaf(W11[k], v[j + k].x, o1);
                        o2 = fmaf(W11[k], v[j + k].y, o2);
                    }
                    q[j] = fmaf(o1, o1, o2 * o2);
                    p[j] = o1 * o2;
                }
            }
            {
                float2 v[14];
#pragma unroll
                for (int t = 0; t < 14; t++) v[t] = pv[(r0 + t) * MS2 + c];
#pragma unroll
                for (int j = 0; j < 4; j++) {
                    float oss = 0.f, ogr = 0.f;
#pragma unroll
                    for (int k = 0; k < 11; k++) {
                        oss = fmaf(W11[k], v[j + k].x, oss);
                        ogr = fmaf(W11[k], v[j + k].y, ogr);
                    }
                    float num = fmaf(2.f, p[j], C1F) * fmaf(2.f, ogr - p[j], C2F);
                    float den = (q[j] + C1F) * (oss - q[j] + C2F);
                    lsum += __fdividef(num, den);
                }
            }
        }
    }

    // ---- Block reduction (fp32), once per persistent block ----
#pragma unroll
    for (int off = 16; off > 0; off >>= 1)
        lsum += __shfl_xor_sync(0xffffffffu, lsum, off);
    if (lane == 0) wsum[wrp] = lsum;
    __syncthreads();

    if (tid == 0) {
        float s = 0.f;
#pragma unroll
        for (int i = 0; i < 8; i++) s += wsum[i];
        g_partials[bid] = s;
        __threadfence();
        unsigned int t = atomicAdd(&g_count, 1u);
        is_last = (t == (unsigned)(NPERS - 1));
    }
    __syncthreads();

    // ---- Last block: deterministic final reduction ----
    if (is_last) {
        __threadfence();
        double acc = 0.0;
        for (int i = tid; i < NPERS; i += NT)
            acc += (double)g_partials[i];
#pragma unroll
        for (int off = 16; off > 0; off >>= 1)
            acc += __shfl_xor_sync(0xffffffffu, acc, off);
        if (lane == 0) dsum[wrp] = acc;
        __syncthreads();
        if (tid == 0) {
            double s = 0.0;
#pragma unroll
            for (int i = 0; i < 8; i++) s += dsum[i];
            out[0] = (float)(1.0 - s / NPIX);
            g_count = 0;   // self-reset -> graph-replay deterministic
        }
    }
}

extern "C" void kernel_launch(void* const* d_in, const int* in_sizes, int n_in,
                              void* d_out, int out_size) {
    const float* gen = (const float*)d_in[0];
    const float* ref = (const float*)d_in[1];
    float* out = (float*)d_out;

    ssim_main<<<NPERS, NT>>>(gen, ref, out);
}